// round 15
// baseline (speedup 1.0000x reference)
#include <cuda_runtime.h>
#include <cstdint>
#include <cstddef>

#define TSTEPS 500
#define BATCH  128

// smem float offsets
#define OWA  0
#define OW1I 6240
#define OW1H 12480
#define OW2I 18720
#define OW2H 24960
#define OWR  31200
#define OQ   33280
#define OSC  33536
#define OSP  33792
#define OT0  34816
#define OT1  43136
#define SMEMF 51456   /* 205,824 bytes */

__device__ float g_X1[64000 * 256];   // prenet hidden, then encW
__device__ float g_X2[64000 * 128];
__device__ float g_GIA[64000 * 768];
__device__ float g_encT[128 * 256 * 256];
__device__ float g_ALN[64000 * 256];
__device__ float g_Y2ALL[64000 * 256];
__device__ float g_HA[2][128 * 256];
__device__ float g_H1[128 * 256];
__device__ float g_H2[128 * 256];
__device__ float g_CTX[128 * 256];
__device__ float g_DEC[128 * 256];
__device__ float g_Y1[128 * 256];
__device__ unsigned g_flag[128 * 32];
__device__ unsigned g_ggen[4 * 32];

typedef unsigned long long ull;

__device__ __forceinline__ ull ffma2(ull a, ull b, ull c) {
    ull d;
    asm("fma.rn.f32x2 %0, %1, %2, %3;" : "=l"(d) : "l"(a), "l"(b), "l"(c));
    return d;
}
__device__ __forceinline__ float unpack_sum(ull v) {
    float2 f = *(float2*)&v;
    return f.x + f.y;
}

template <bool RELU, bool HASB>
__global__ __launch_bounds__(256) void gemm_k(const float* __restrict__ A,
                                              const float* __restrict__ W,
                                              const float* __restrict__ bias,
                                              float* __restrict__ C, int K, int N, int ldw) {
    __shared__ float As[16 * 68];
    __shared__ float Ws[16 * 68];
    const int m0 = blockIdx.x * 64, n0 = blockIdx.y * 64;
    const int tid = threadIdx.x, tx = tid & 15, ty = tid >> 4;
    float acc[4][4] = {};
    for (int k0 = 0; k0 < K; k0 += 16) {
        int idx = tid;
#pragma unroll
        for (int it = 0; it < 4; it++) {
            int m = idx >> 4, k = idx & 15;
            As[k * 68 + m] = A[(size_t)(m0 + m) * K + k0 + k];
            int wr = n0 + m;
            Ws[k * 68 + m] = (wr < N) ? W[(size_t)wr * ldw + k0 + k] : 0.f;
            idx += 256;
        }
        __syncthreads();
#pragma unroll
        for (int k = 0; k < 16; k++) {
            float4 a = *(const float4*)&As[k * 68 + ty * 4];
            float4 w = *(const float4*)&Ws[k * 68 + tx * 4];
            acc[0][0] += a.x * w.x; acc[0][1] += a.x * w.y; acc[0][2] += a.x * w.z; acc[0][3] += a.x * w.w;
            acc[1][0] += a.y * w.x; acc[1][1] += a.y * w.y; acc[1][2] += a.y * w.z; acc[1][3] += a.y * w.w;
            acc[2][0] += a.z * w.x; acc[2][1] += a.z * w.y; acc[2][2] += a.z * w.z; acc[2][3] += a.z * w.w;
            acc[3][0] += a.w * w.x; acc[3][1] += a.w * w.y; acc[3][2] += a.w * w.z; acc[3][3] += a.w * w.w;
        }
        __syncthreads();
    }
#pragma unroll
    for (int i = 0; i < 4; i++) {
        int m = m0 + ty * 4 + i;
#pragma unroll
        for (int j = 0; j < 4; j++) {
            int col = n0 + tx * 4 + j;
            if (col < N) {
                float v = acc[i][j] + (HASB ? bias[col] : 0.f);
                if (RELU) v = fmaxf(v, 0.f);
                C[(size_t)m * N + col] = v;
            }
        }
    }
}

__global__ void transpose_enc_k(const float* __restrict__ enc) {
    __shared__ float tile[32][33];
    const int b = blockIdx.x, l0 = blockIdx.y * 32, d0 = blockIdx.z * 32;
    const int j = threadIdx.x & 31, i0 = threadIdx.x >> 5;
    const float* base = enc + (size_t)b * 65536;
#pragma unroll
    for (int ii = 0; ii < 32; ii += 8)
        tile[i0 + ii][j] = base[(size_t)(l0 + i0 + ii) * 256 + d0 + j];
    __syncthreads();
    float* ob = g_encT + (size_t)b * 65536;
#pragma unroll
    for (int ii = 0; ii < 32; ii += 8)
        ob[(size_t)(d0 + i0 + ii) * 256 + l0 + j] = tile[j][i0 + ii];
}

__global__ void transpose_aln_k(float* __restrict__ out) {
    __shared__ float tile[32][33];
    const int b = blockIdx.x, l0 = blockIdx.y * 32, t0 = blockIdx.z * 32;
    const int j = threadIdx.x & 31, i0 = threadIdx.x >> 5;
#pragma unroll
    for (int ii = 0; ii < 32; ii += 8) {
        int t = t0 + i0 + ii;
        if (t < TSTEPS) tile[i0 + ii][j] = g_ALN[((size_t)t * BATCH + b) * 256 + l0 + j];
    }
    __syncthreads();
#pragma unroll
    for (int ii = 0; ii < 32; ii += 8) {
        int t = t0 + j, l = l0 + i0 + ii;
        if (t < TSTEPS) out[((size_t)b * 256 + l) * TSTEPS + t] = tile[j][i0 + ii];
    }
}

__device__ __forceinline__ float sigm(float x) { return 1.f / (1.f + expf(-x)); }

__device__ __forceinline__ void groupbar(unsigned& lgen, int grp, int cj) {
    __syncthreads();
    lgen++;
    if (cj == 0) {
        if (threadIdx.x >= 1 && threadIdx.x < 32) {
            const unsigned* f = &g_flag[(grp * 32 + threadIdx.x) * 32];
            unsigned v;
            do {
                asm volatile("ld.acquire.gpu.global.u32 %0, [%1];" : "=r"(v) : "l"(f) : "memory");
            } while ((int)(v - lgen) < 0);
        }
        __syncthreads();
        if (threadIdx.x == 0)
            asm volatile("st.release.gpu.global.u32 [%0], %1;"
                         :: "l"(&g_ggen[grp * 32]), "r"(lgen) : "memory");
    } else {
        if (threadIdx.x == 0) {
            asm volatile("st.release.gpu.global.u32 [%0], %1;"
                         :: "l"(&g_flag[blockIdx.x * 32]), "r"(lgen) : "memory");
            unsigned v;
            do {
                asm volatile("ld.acquire.gpu.global.u32 %0, [%1];"
                             : "=r"(v) : "l"(&g_ggen[grp * 32]) : "memory");
            } while ((int)(v - lgen) < 0);
        }
        __syncthreads();
    }
}

__device__ __forceinline__ void load_A32(const float* __restrict__ src, int b0, float* As) {
    for (int idx = threadIdx.x; idx < 32 * 64; idx += 256) {
        int r = idx >> 6, q = idx & 63;
        *(float4*)(As + r * 260 + q * 4) = *(const float4*)(src + (size_t)(b0 + r) * 256 + q * 4);
    }
}

__device__ __forceinline__ void load_A32sum(const float* __restrict__ sa,
                                            const float* __restrict__ sb, int b0, float* As) {
    for (int idx = threadIdx.x; idx < 32 * 64; idx += 256) {
        int r = idx >> 6, q = idx & 63;
        float4 a = *(const float4*)(sa + (size_t)(b0 + r) * 256 + q * 4);
        float4 b = *(const float4*)(sb + (size_t)(b0 + r) * 256 + q * 4);
        a.x += b.x; a.y += b.y; a.z += b.z; a.w += b.w;
        *(float4*)(As + r * 260 + q * 4) = a;
    }
}

__device__ __forceinline__ void preload_W24(const float* __restrict__ w, int c0, float* Wd) {
    for (int idx = threadIdx.x; idx < 24 * 64; idx += 256) {
        int row = idx >> 6, q = idx & 63;
        int g = row >> 3, i = row & 7;
        *(float4*)(Wd + row * 260 + q * 4) =
            *(const float4*)(w + (size_t)(g * 256 + c0 + i) * 256 + q * 4);
    }
}

__device__ __forceinline__ void gate3(const float* As, const float* Ws, int r, int cg, float out[3]) {
    const ulonglong2* a8 = (const ulonglong2*)(As + r * 260);
    const ulonglong2* w0 = (const ulonglong2*)(Ws + cg * 260);
    const ulonglong2* w1 = (const ulonglong2*)(Ws + (8 + cg) * 260);
    const ulonglong2* w2 = (const ulonglong2*)(Ws + (16 + cg) * 260);
    ull acc0 = 0, acc1 = 0, acc2 = 0;
#pragma unroll 8
    for (int k = 0; k < 64; k++) {
        ulonglong2 a = a8[k];
        ulonglong2 b0 = w0[k], b1 = w1[k], b2 = w2[k];
        acc0 = ffma2(a.x, b0.x, acc0); acc0 = ffma2(a.y, b0.y, acc0);
        acc1 = ffma2(a.x, b1.x, acc1); acc1 = ffma2(a.y, b1.y, acc1);
        acc2 = ffma2(a.x, b2.x, acc2); acc2 = ffma2(a.y, b2.y, acc2);
    }
    out[0] = unpack_sum(acc0);
    out[1] = unpack_sum(acc1);
    out[2] = unpack_sum(acc2);
}

// block softmax over 256 values (one per thread); returns normalized weight
__device__ __forceinline__ float softmax256(float s) {
    __shared__ float red[8];
    __shared__ float redv[2];
    const int tid = threadIdx.x;
    float m = s;
#pragma unroll
    for (int off = 16; off > 0; off >>= 1) m = fmaxf(m, __shfl_xor_sync(~0u, m, off));
    if ((tid & 31) == 0) red[tid >> 5] = m;
    __syncthreads();
    if (tid < 8) {
        float x = red[tid];
#pragma unroll
        for (int off = 4; off > 0; off >>= 1) x = fmaxf(x, __shfl_xor_sync(0xffu, x, off));
        if (tid == 0) redv[0] = x;
    }
    __syncthreads();
    float e = expf(s - redv[0]);
    float su = e;
#pragma unroll
    for (int off = 16; off > 0; off >>= 1) su += __shfl_xor_sync(~0u, su, off);
    if ((tid & 31) == 0) red[tid >> 5] = su;
    __syncthreads();
    if (tid < 8) {
        float x = red[tid];
#pragma unroll
        for (int off = 4; off > 0; off >>= 1) x += __shfl_xor_sync(0xffu, x, off);
        if (tid == 0) redv[1] = x;
    }
    __syncthreads();
    return e / redv[1];
}

// scores sweep partials into SP: thread=(l4, dq); q in smem
__device__ __forceinline__ void scores_sweep(int b, const float* Q, float* SP) {
    const int tid = threadIdx.x;
    const int l4 = (tid & 63) * 4, dq = tid >> 6;
    const float* ep = g_encT + (size_t)b * 65536 + (size_t)(dq * 64) * 256 + l4;
    const float* qq = Q + dq * 64;
    float4 s4 = {0.f, 0.f, 0.f, 0.f};
#pragma unroll 8
    for (int d = 0; d < 64; d++) {
        float4 v = *(const float4*)(ep + d * 256);
        float qv = qq[d];
        s4.x += qv * v.x; s4.y += qv * v.y; s4.z += qv * v.z; s4.w += qv * v.w;
    }
    *(float4*)(SP + dq * 256 + l4) = s4;
}

// ctx sweep partials into SP: thread=(d4, lq); weights from SC (align)
__device__ __forceinline__ void ctx_sweep(int b, const float* SC, float* SP) {
    const int tid = threadIdx.x;
    const int d4 = (tid & 63) * 4, lq = tid >> 6;
    const float* ew = g_X1 + (size_t)b * 65536 + (size_t)(lq * 64) * 256 + d4;
    const float* ss = SC + lq * 64;
    float4 c4 = {0.f, 0.f, 0.f, 0.f};
#pragma unroll 8
    for (int l = 0; l < 64; l++) {
        float4 v = *(const float4*)(ew + l * 256);
        float sv = ss[l];
        c4.x += sv * v.x; c4.y += sv * v.y; c4.z += sv * v.z; c4.w += sv * v.w;
    }
    *(float4*)(SP + lq * 256 + d4) = c4;
}

__global__ __launch_bounds__(256) void decoder_loop(
    const float* __restrict__ attn_bhh,
    const float* __restrict__ proj1_b,
    const float* __restrict__ rnn1_bih, const float* __restrict__ rnn1_bhh,
    const float* __restrict__ rnn2_bih, const float* __restrict__ rnn2_bhh,
    const float* __restrict__ attn_whh,
    const float* __restrict__ proj1_w,
    const float* __restrict__ rnn1_wih, const float* __restrict__ rnn1_whh,
    const float* __restrict__ rnn2_wih, const float* __restrict__ rnn2_whh) {
    extern __shared__ float sm[];
    const int tid = threadIdx.x;
    const int grp = blockIdx.x >> 5, cj = blockIdx.x & 31;
    const int b0 = grp * 32, c0 = cj * 8;
    const int b = b0 + cj;
    const int r = tid >> 3, cg = tid & 7, c = c0 + cg;
    const int bm = b0 + r;
    float* Q  = sm + OQ;
    float* SC = sm + OSC;
    float* SP = sm + OSP;
    float* T0 = sm + OT0;
    float* T1 = sm + OT1;
    unsigned lgen;
    asm volatile("ld.acquire.gpu.global.u32 %0, [%1];" : "=r"(lgen) : "l"(&g_ggen[grp * 32]) : "memory");

    preload_W24(attn_whh, c0, sm + OWA);
    preload_W24(rnn1_wih, c0, sm + OW1I);
    preload_W24(rnn1_whh, c0, sm + OW1H);
    preload_W24(rnn2_wih, c0, sm + OW2I);
    preload_W24(rnn2_whh, c0, sm + OW2H);
    for (int idx = tid; idx < 8 * 64; idx += 256) {
        int row = idx >> 6, qq = idx & 63;
        *(float4*)(sm + OWR + row * 260 + qq * 4) =
            *(const float4*)(proj1_w + (size_t)(c0 + row) * 512 + 256 + qq * 4);
    }
    // P0: zero states, hA(0) = attnGRU(0, gia(0))
    {
        int i = blockIdx.x * 256 + tid;
        g_H1[i] = 0.f;
        g_H2[i] = 0.f;
        const float* gb = g_GIA + ((size_t)bm * TSTEPS) * 768;
        float rr = sigm(gb[c] + attn_bhh[c]);
        float zz = sigm(gb[256 + c] + attn_bhh[256 + c]);
        float nn = tanhf(gb[512 + c] + rr * attn_bhh[512 + c]);
        g_HA[0][(size_t)bm * 256 + c] = (1.f - zz) * nn;
    }
    float gh1[3] = { rnn1_bhh[c], rnn1_bhh[256 + c], rnn1_bhh[512 + c] };
    float gh2[3];
    groupbar(lgen, grp, cj);
    // P1: scores(0) + softmax -> align(0)
    Q[tid] = g_HA[0][(size_t)b * 256 + tid];
    __syncthreads();
    scores_sweep(b, Q, SP);
    __syncthreads();
    {
        float s = (SP[tid] + SP[256 + tid]) + (SP[512 + tid] + SP[768 + tid]);
        float w = softmax256(s);
        SC[tid] = w;
        g_ALN[(size_t)b * 256 + tid] = w;   // t = 0
    }
    groupbar(lgen, grp, cj);
    // P2: ctx(0), attnGRU -> hA(1), hWr(0) -> DEC(0)
    ctx_sweep(b, SC, SP);
    load_A32(g_HA[0], b0, T0);
    __syncthreads();
    g_CTX[(size_t)b * 256 + tid] = (SP[tid] + SP[256 + tid]) + (SP[512 + tid] + SP[768 + tid]);
    {
        float acc[3];
        gate3(T0, sm + OWA, r, cg, acc);
        const float* gb = g_GIA + ((size_t)bm * TSTEPS + 1) * 768;
        float rr = sigm(gb[c] + acc[0] + attn_bhh[c]);
        float zz = sigm(gb[256 + c] + acc[1] + attn_bhh[256 + c]);
        float nn = tanhf(gb[512 + c] + rr * (acc[2] + attn_bhh[512 + c]));
        float hp = T0[r * 260 + c];
        g_HA[1][(size_t)bm * 256 + c] = (1.f - zz) * nn + zz * hp;
    }
    {
        const ulonglong2* a8 = (const ulonglong2*)(T0 + r * 260);
        const ulonglong2* w8 = (const ulonglong2*)(sm + OWR + cg * 260);
        ull acc = 0;
#pragma unroll 8
        for (int k = 0; k < 64; k++) {
            ulonglong2 a = a8[k], w2 = w8[k];
            acc = ffma2(a.x, w2.x, acc); acc = ffma2(a.y, w2.y, acc);
        }
        g_DEC[(size_t)bm * 256 + c] = unpack_sum(acc) + proj1_b[c];
    }
    groupbar(lgen, grp, cj);

    for (int t = 0; t < TSTEPS; t++) {
        const int tp1 = t + 1, tp2 = t + 2;
        // ===== A(t): scores(t+1) + rnn1(t) + gh2 + softmax =====
        float hp1 = g_H1[(size_t)bm * 256 + c];
        if (tp1 < TSTEPS) Q[tid] = g_HA[tp1 & 1][(size_t)b * 256 + tid];
        load_A32sum(g_CTX, g_DEC, b0, T0);
        load_A32(g_H2, b0, T1);
        __syncthreads();
        if (tp1 < TSTEPS) scores_sweep(b, Q, SP);
        __syncthreads();
        {
            float acc[3];
            gate3(T0, sm + OW1I, r, cg, acc);
            float rr = sigm(acc[0] + rnn1_bih[c] + gh1[0]);
            float zz = sigm(acc[1] + rnn1_bih[256 + c] + gh1[1]);
            float nn = tanhf(acc[2] + rnn1_bih[512 + c] + rr * gh1[2]);
            float hn = (1.f - zz) * nn + zz * hp1;
            g_H1[(size_t)bm * 256 + c] = hn;
            g_Y1[(size_t)bm * 256 + c] = T0[r * 260 + c] + hn;
        }
        gate3(T1, sm + OW2H, r, cg, gh2);
        gh2[0] += rnn2_bhh[c]; gh2[1] += rnn2_bhh[256 + c]; gh2[2] += rnn2_bhh[512 + c];
        if (tp1 < TSTEPS) {
            float s = (SP[tid] + SP[256 + tid]) + (SP[512 + tid] + SP[768 + tid]);
            float w = softmax256(s);
            SC[tid] = w;
            g_ALN[((size_t)tp1 * BATCH + b) * 256 + tid] = w;
        }
        groupbar(lgen, grp, cj);
        // ===== B(t): ctx(t+1) + rnn2(t) + gh1(t+1) + attnGRU(t+2) + hWr(t+1)
        float hp2 = g_H2[(size_t)bm * 256 + c];
        float gb0 = 0.f, gb1 = 0.f, gb2 = 0.f;
        if (tp2 < TSTEPS) {
            const float* gb = g_GIA + ((size_t)bm * TSTEPS + tp2) * 768;
            gb0 = gb[c]; gb1 = gb[256 + c]; gb2 = gb[512 + c];
        }
        if (tp1 < TSTEPS) ctx_sweep(b, SC, SP);
        load_A32(g_Y1, b0, T0);
        load_A32(g_H1, b0, T1);
        __syncthreads();
        {
            float acc[3];
            gate3(T0, sm + OW2I, r, cg, acc);
            float rr = sigm(acc[0] + rnn2_bih[c] + gh2[0]);
            float zz = sigm(acc[1] + rnn2_bih[256 + c] + gh2[1]);
            float nn = tanhf(acc[2] + rnn2_bih[512 + c] + rr * gh2[2]);
            float hn = (1.f - zz) * nn + zz * hp2;
            g_H2[(size_t)bm * 256 + c] = hn;
            g_Y2ALL[((size_t)bm * TSTEPS + t) * 256 + c] = T0[r * 260 + c] + hn;
        }
        gate3(T1, sm + OW1H, r, cg, gh1);
        gh1[0] += rnn1_bhh[c]; gh1[1] += rnn1_bhh[256 + c]; gh1[2] += rnn1_bhh[512 + c];
        if (tp1 < TSTEPS) {
            g_CTX[(size_t)b * 256 + tid] =
                (SP[tid] + SP[256 + tid]) + (SP[512 + tid] + SP[768 + tid]);
            __syncthreads();
            load_A32(g_HA[tp1 & 1], b0, T0);
            __syncthreads();
            if (tp2 < TSTEPS) {
                float acc[3];
                gate3(T0, sm + OWA, r, cg, acc);
                float rr = sigm(gb0 + acc[0] + attn_bhh[c]);
                float zz = sigm(gb1 + acc[1] + attn_bhh[256 + c]);
                float nn = tanhf(gb2 + rr * (acc[2] + attn_bhh[512 + c]));
                float hp = T0[r * 260 + c];
                g_HA[t & 1][(size_t)bm * 256 + c] = (1.f - zz) * nn + zz * hp;
            }
            {
                const ulonglong2* a8 = (const ulonglong2*)(T0 + r * 260);
                const ulonglong2* w8 = (const ulonglong2*)(sm + OWR + cg * 260);
                ull acc = 0;
#pragma unroll 8
                for (int k = 0; k < 64; k++) {
                    ulonglong2 a = a8[k], w2 = w8[k];
                    acc = ffma2(a.x, w2.x, acc); acc = ffma2(a.y, w2.y, acc);
                }
                g_DEC[(size_t)bm * 256 + c] = unpack_sum(acc) + proj1_b[c];
            }
        }
        groupbar(lgen, grp, cj);
    }
}

extern "C" void kernel_launch(void* const* d_in, const int* in_sizes, int n_in,
                              void* d_out, int out_size) {
    const float* dec      = (const float*)d_in[0];
    const float* enc      = (const float*)d_in[1];
    const float* pre_w1   = (const float*)d_in[2];
    const float* pre_b1   = (const float*)d_in[3];
    const float* pre_w2   = (const float*)d_in[4];
    const float* pre_b2   = (const float*)d_in[5];
    const float* attn_wih = (const float*)d_in[6];
    const float* attn_whh = (const float*)d_in[7];
    const float* attn_bih = (const float*)d_in[8];
    const float* attn_bhh = (const float*)d_in[9];
    const float* proj1_w  = (const float*)d_in[10];
    const float* proj1_b  = (const float*)d_in[11];
    const float* rnn1_wih = (const float*)d_in[12];
    const float* rnn1_whh = (const float*)d_in[13];
    const float* rnn1_bih = (const float*)d_in[14];
    const float* rnn1_bhh = (const float*)d_in[15];
    const float* rnn2_wih = (const float*)d_in[16];
    const float* rnn2_whh = (const float*)d_in[17];
    const float* rnn2_bih = (const float*)d_in[18];
    const float* rnn2_bhh = (const float*)d_in[19];
    const float* proj2_w  = (const float*)d_in[20];
    const float* proj2_b  = (const float*)d_in[21];
    float* out = (float*)d_out;

    float *x1, *x2, *gia, *y2all;
    cudaGetSymbolAddress((void**)&x1, g_X1);
    cudaGetSymbolAddress((void**)&x2, g_X2);
    cudaGetSymbolAddress((void**)&gia, g_GIA);
    cudaGetSymbolAddress((void**)&y2all, g_Y2ALL);

    const int SMEM = SMEMF * 4;
    cudaFuncSetAttribute(decoder_loop, cudaFuncAttributeMaxDynamicSharedMemorySize, SMEM);

    transpose_enc_k<<<dim3(128, 8, 8), 256>>>(enc);
    gemm_k<true, true><<<dim3(1000, 4), 256>>>(dec, pre_w1, pre_b1, x1, 80, 256, 80);
    gemm_k<true, true><<<dim3(1000, 2), 256>>>(x1, pre_w2, pre_b2, x2, 256, 128, 256);
    gemm_k<false, true><<<dim3(1000, 12), 256>>>(x2, attn_wih, attn_bih, gia, 128, 768, 128);
    gemm_k<false, false><<<dim3(512, 4), 256>>>(enc, proj1_w, nullptr, x1, 256, 256, 512);
    decoder_loop<<<128, 256, SMEM>>>(attn_bhh, proj1_b,
                                     rnn1_bih, rnn1_bhh, rnn2_bih, rnn2_bhh,
                                     attn_whh, proj1_w,
                                     rnn1_wih, rnn1_whh, rnn2_wih, rnn2_whh);
    gemm_k<false, true><<<dim3(1000, 3), 256>>>(y2all, proj2_w, proj2_b, out, 256, 160, 256);
    transpose_aln_k<<<dim3(128, 8, 16), 256>>>(out + 10240000);
}

// round 16
// speedup vs baseline: 1.0484x; 1.0484x over previous
#include <cuda_runtime.h>
#include <cstdint>
#include <cstddef>

#define TSTEPS 500
#define BATCH  128

// smem float offsets (decoder_loop)
#define OWA  0
#define OW1I 6240
#define OW1H 12480
#define OW2I 18720
#define OW2H 24960
#define OWR  31200
#define OST  33280
#define OT1  41600
#define SMEMF 49920   /* 199,680 bytes */

__device__ float g_ENCW[128 * 256 * 256];  // enc @ proj1_w[:, :256]^T, [b][l][d]
__device__ float g_GIA[64000 * 768];
__device__ float g_encT[128 * 256 * 256];
__device__ float g_ALN[64000 * 256];
__device__ float g_Y2ALL[64000 * 256];
__device__ float g_HA[2][128 * 256];
__device__ float g_H1[128 * 256];
__device__ float g_H2[128 * 256];
__device__ float g_CTX[128 * 256];
__device__ float g_DEC[128 * 256];
__device__ float g_Y1[128 * 256];
__device__ unsigned g_flag[128 * 32];
__device__ unsigned g_ggen[4 * 32];

typedef unsigned long long ull;

__device__ __forceinline__ ull ffma2(ull a, ull b, ull c) {
    ull d;
    asm("fma.rn.f32x2 %0, %1, %2, %3;" : "=l"(d) : "l"(a), "l"(b), "l"(c));
    return d;
}
__device__ __forceinline__ float unpack_sum(ull v) {
    float2 f = *(float2*)&v;
    return f.x + f.y;
}

// ---------------- generic tiled GEMM (pre/post passes) ----------------------
template <bool RELU, bool HASB>
__global__ __launch_bounds__(256) void gemm_k(const float* __restrict__ A,
                                              const float* __restrict__ W,
                                              const float* __restrict__ bias,
                                              float* __restrict__ C, int K, int N, int ldw) {
    __shared__ float As[16 * 68];
    __shared__ float Ws[16 * 68];
    const int m0 = blockIdx.x * 64, n0 = blockIdx.y * 64;
    const int tid = threadIdx.x, tx = tid & 15, ty = tid >> 4;
    float acc[4][4] = {};
    for (int k0 = 0; k0 < K; k0 += 16) {
        int idx = tid;
#pragma unroll
        for (int it = 0; it < 4; it++) {
            int m = idx >> 4, k = idx & 15;
            As[k * 68 + m] = A[(size_t)(m0 + m) * K + k0 + k];
            int wr = n0 + m;
            Ws[k * 68 + m] = (wr < N) ? W[(size_t)wr * ldw + k0 + k] : 0.f;
            idx += 256;
        }
        __syncthreads();
#pragma unroll
        for (int k = 0; k < 16; k++) {
            float4 a = *(const float4*)&As[k * 68 + ty * 4];
            float4 w = *(const float4*)&Ws[k * 68 + tx * 4];
            acc[0][0] += a.x * w.x; acc[0][1] += a.x * w.y; acc[0][2] += a.x * w.z; acc[0][3] += a.x * w.w;
            acc[1][0] += a.y * w.x; acc[1][1] += a.y * w.y; acc[1][2] += a.y * w.z; acc[1][3] += a.y * w.w;
            acc[2][0] += a.z * w.x; acc[2][1] += a.z * w.y; acc[2][2] += a.z * w.z; acc[2][3] += a.z * w.w;
            acc[3][0] += a.w * w.x; acc[3][1] += a.w * w.y; acc[3][2] += a.w * w.z; acc[3][3] += a.w * w.w;
        }
        __syncthreads();
    }
#pragma unroll
    for (int i = 0; i < 4; i++) {
        int m = m0 + ty * 4 + i;
#pragma unroll
        for (int j = 0; j < 4; j++) {
            int col = n0 + tx * 4 + j;
            if (col < N) {
                float v = acc[i][j] + (HASB ? bias[col] : 0.f);
                if (RELU) v = fmaxf(v, 0.f);
                C[(size_t)m * N + col] = v;
            }
        }
    }
}

// ---------------- fused prenet: dec -> h1 -> x2 -> gia ----------------------
template <bool RELU>
__device__ __forceinline__ void block_gemm64(const float* __restrict__ A, int lda,
                                             const float* __restrict__ W, int ldw,
                                             const float* __restrict__ bias,
                                             float* __restrict__ C, int ldc,
                                             int K, int N, float* As, float* Ws) {
    const int tid = threadIdx.x, tx = tid & 15, ty = tid >> 4;
    for (int n0 = 0; n0 < N; n0 += 64) {
        float acc[4][4] = {};
        for (int k0 = 0; k0 < K; k0 += 16) {
            int idx = tid;
#pragma unroll
            for (int it = 0; it < 4; it++) {
                int m = idx >> 4, k = idx & 15;
                As[k * 68 + m] = A[(size_t)m * lda + k0 + k];
                Ws[k * 68 + m] = W[(size_t)(n0 + m) * ldw + k0 + k];
                idx += 256;
            }
            __syncthreads();
#pragma unroll
            for (int k = 0; k < 16; k++) {
                float4 a = *(const float4*)&As[k * 68 + ty * 4];
                float4 w = *(const float4*)&Ws[k * 68 + tx * 4];
                acc[0][0] += a.x * w.x; acc[0][1] += a.x * w.y; acc[0][2] += a.x * w.z; acc[0][3] += a.x * w.w;
                acc[1][0] += a.y * w.x; acc[1][1] += a.y * w.y; acc[1][2] += a.y * w.z; acc[1][3] += a.y * w.w;
                acc[2][0] += a.z * w.x; acc[2][1] += a.z * w.y; acc[2][2] += a.z * w.z; acc[2][3] += a.z * w.w;
                acc[3][0] += a.w * w.x; acc[3][1] += a.w * w.y; acc[3][2] += a.w * w.z; acc[3][3] += a.w * w.w;
            }
            __syncthreads();
        }
#pragma unroll
        for (int i = 0; i < 4; i++) {
            int m = ty * 4 + i;
#pragma unroll
            for (int j = 0; j < 4; j++) {
                float v = acc[i][j] + bias[n0 + tx * 4 + j];
                if (RELU) v = fmaxf(v, 0.f);
                C[(size_t)m * ldc + n0 + tx * 4 + j] = v;
            }
        }
        __syncthreads();
    }
}

__global__ __launch_bounds__(256) void prenet_fused_k(
    const float* __restrict__ dec,
    const float* __restrict__ w1, const float* __restrict__ b1,
    const float* __restrict__ w2, const float* __restrict__ b2,
    const float* __restrict__ w3, const float* __restrict__ b3,
    float* __restrict__ gia) {
    extern __shared__ float psm[];
    float* h1 = psm;                 // 64*256
    float* x2 = psm + 64 * 256;      // 64*128
    float* As = psm + 64 * 384;
    float* Ws = As + 16 * 68;
    const float* Arow = dec + (size_t)blockIdx.x * 64 * 80;
    block_gemm64<true>(Arow, 80, w1, 80, b1, h1, 256, 80, 256, As, Ws);
    __syncthreads();
    block_gemm64<true>(h1, 256, w2, 256, b2, x2, 128, 256, 128, As, Ws);
    __syncthreads();
    block_gemm64<false>(x2, 128, w3, 128, b3,
                        gia + (size_t)blockIdx.x * 64 * 768, 768, 128, 768, As, Ws);
}

// ---------------- transposes -----------------------------------------------
__global__ void transpose_enc_k(const float* __restrict__ enc) {
    __shared__ float tile[32][33];
    const int b = blockIdx.x, l0 = blockIdx.y * 32, d0 = blockIdx.z * 32;
    const int j = threadIdx.x & 31, i0 = threadIdx.x >> 5;
    const float* base = enc + (size_t)b * 65536;
#pragma unroll
    for (int ii = 0; ii < 32; ii += 8)
        tile[i0 + ii][j] = base[(size_t)(l0 + i0 + ii) * 256 + d0 + j];
    __syncthreads();
    float* ob = g_encT + (size_t)b * 65536;
#pragma unroll
    for (int ii = 0; ii < 32; ii += 8)
        ob[(size_t)(d0 + i0 + ii) * 256 + l0 + j] = tile[j][i0 + ii];
}

__global__ void transpose_aln_k(float* __restrict__ out) {
    __shared__ float tile[32][33];
    const int b = blockIdx.x, l0 = blockIdx.y * 32, t0 = blockIdx.z * 32;
    const int j = threadIdx.x & 31, i0 = threadIdx.x >> 5;
#pragma unroll
    for (int ii = 0; ii < 32; ii += 8) {
        int t = t0 + i0 + ii;
        if (t < TSTEPS) tile[i0 + ii][j] = g_ALN[((size_t)t * BATCH + b) * 256 + l0 + j];
    }
    __syncthreads();
#pragma unroll
    for (int ii = 0; ii < 32; ii += 8) {
        int t = t0 + j, l = l0 + i0 + ii;
        if (t < TSTEPS) out[((size_t)b * 256 + l) * TSTEPS + t] = tile[j][i0 + ii];
    }
}

// ---------------- loop helpers ----------------------------------------------
__device__ __forceinline__ float sigm(float x) { return 1.f / (1.f + expf(-x)); }

__device__ __forceinline__ void groupbar(unsigned& lgen, int grp, int cj) {
    __syncthreads();
    lgen++;
    if (cj == 0) {
        if (threadIdx.x >= 1 && threadIdx.x < 32) {
            const unsigned* f = &g_flag[(grp * 32 + threadIdx.x) * 32];
            unsigned v;
            do {
                asm volatile("ld.acquire.gpu.global.u32 %0, [%1];" : "=r"(v) : "l"(f) : "memory");
            } while ((int)(v - lgen) < 0);
        }
        __syncthreads();
        if (threadIdx.x == 0)
            asm volatile("st.release.gpu.global.u32 [%0], %1;"
                         :: "l"(&g_ggen[grp * 32]), "r"(lgen) : "memory");
    } else {
        if (threadIdx.x == 0) {
            asm volatile("st.release.gpu.global.u32 [%0], %1;"
                         :: "l"(&g_flag[blockIdx.x * 32]), "r"(lgen) : "memory");
            unsigned v;
            do {
                asm volatile("ld.acquire.gpu.global.u32 %0, [%1];"
                             : "=r"(v) : "l"(&g_ggen[grp * 32]) : "memory");
            } while ((int)(v - lgen) < 0);
        }
        __syncthreads();
    }
}

__device__ __forceinline__ void load_A32(const float* __restrict__ src, int b0, float* As) {
    for (int idx = threadIdx.x; idx < 32 * 64; idx += 256) {
        int r = idx >> 6, q = idx & 63;
        *(float4*)(As + r * 260 + q * 4) = *(const float4*)(src + (size_t)(b0 + r) * 256 + q * 4);
    }
}

__device__ __forceinline__ void load_A32sum(const float* __restrict__ sa,
                                            const float* __restrict__ sb, int b0, float* As) {
    for (int idx = threadIdx.x; idx < 32 * 64; idx += 256) {
        int r = idx >> 6, q = idx & 63;
        float4 a = *(const float4*)(sa + (size_t)(b0 + r) * 256 + q * 4);
        float4 b = *(const float4*)(sb + (size_t)(b0 + r) * 256 + q * 4);
        a.x += b.x; a.y += b.y; a.z += b.z; a.w += b.w;
        *(float4*)(As + r * 260 + q * 4) = a;
    }
}

__device__ __forceinline__ void preload_W24(const float* __restrict__ w, int c0, float* Wd) {
    for (int idx = threadIdx.x; idx < 24 * 64; idx += 256) {
        int row = idx >> 6, q = idx & 63;
        int g = row >> 3, i = row & 7;
        *(float4*)(Wd + row * 260 + q * 4) =
            *(const float4*)(w + (size_t)(g * 256 + c0 + i) * 256 + q * 4);
    }
}

__device__ __forceinline__ void gate3(const float* As, const float* Ws, int r, int cg, float out[3]) {
    const ulonglong2* a8 = (const ulonglong2*)(As + r * 260);
    const ulonglong2* w0 = (const ulonglong2*)(Ws + cg * 260);
    const ulonglong2* w1 = (const ulonglong2*)(Ws + (8 + cg) * 260);
    const ulonglong2* w2 = (const ulonglong2*)(Ws + (16 + cg) * 260);
    ull acc0 = 0, acc1 = 0, acc2 = 0;
#pragma unroll 8
    for (int k = 0; k < 64; k++) {
        ulonglong2 a = a8[k];
        ulonglong2 b0 = w0[k], b1 = w1[k], b2 = w2[k];
        acc0 = ffma2(a.x, b0.x, acc0); acc0 = ffma2(a.y, b0.y, acc0);
        acc1 = ffma2(a.x, b1.x, acc1); acc1 = ffma2(a.y, b1.y, acc1);
        acc2 = ffma2(a.x, b2.x, acc2); acc2 = ffma2(a.y, b2.y, acc2);
    }
    out[0] = unpack_sum(acc0);
    out[1] = unpack_sum(acc1);
    out[2] = unpack_sum(acc2);
}

// X(ta): attention(ta) for row b + attnGRU -> hA(ta+1) + hWr(ta)
__device__ void phase_X(int ta, const float* __restrict__ attn_bhh,
                        const float* __restrict__ proj1_b,
                        int b0, int b, int r, int cg, int c, float* sm) {
    const int tid = threadIdx.x;
    const int p = ta & 1;
    float* As = sm + OST;
    float* q = sm + OST;
    float* sc = sm + OST + 256;
    float* sp = sm + OST + 512;
    __shared__ float red[8];
    __shared__ float redv[2];
    __syncthreads();
    q[tid] = g_HA[p][(size_t)b * 256 + tid];
    __syncthreads();
    {   // scores sweep: thread = (l4, dq)
        const int l4 = (tid & 63) * 4, dq = tid >> 6;
        const float* ep = g_encT + (size_t)b * 65536 + (size_t)(dq * 64) * 256 + l4;
        const float* qq = q + dq * 64;
        float4 s4 = {0.f, 0.f, 0.f, 0.f};
#pragma unroll 8
        for (int d = 0; d < 64; d++) {
            float4 v = *(const float4*)(ep + d * 256);
            float qv = qq[d];
            s4.x += qv * v.x; s4.y += qv * v.y; s4.z += qv * v.z; s4.w += qv * v.w;
        }
        *(float4*)(sp + dq * 256 + l4) = s4;
    }
    __syncthreads();
    float s = (sp[tid] + sp[256 + tid]) + (sp[512 + tid] + sp[768 + tid]);
    float m = s;
#pragma unroll
    for (int off = 16; off > 0; off >>= 1) m = fmaxf(m, __shfl_xor_sync(~0u, m, off));
    const int w = tid >> 5;
    if ((tid & 31) == 0) red[w] = m;
    __syncthreads();
    if (tid < 8) {
        float x = red[tid];
#pragma unroll
        for (int off = 4; off > 0; off >>= 1) x = fmaxf(x, __shfl_xor_sync(0xffu, x, off));
        if (tid == 0) redv[0] = x;
    }
    __syncthreads();
    float e = expf(s - redv[0]);
    float su = e;
#pragma unroll
    for (int off = 16; off > 0; off >>= 1) su += __shfl_xor_sync(~0u, su, off);
    if ((tid & 31) == 0) red[w] = su;
    __syncthreads();
    if (tid < 8) {
        float x = red[tid];
#pragma unroll
        for (int off = 4; off > 0; off >>= 1) x += __shfl_xor_sync(0xffu, x, off);
        if (tid == 0) redv[1] = x;
    }
    __syncthreads();
    float wgt = e / redv[1];
    sc[tid] = wgt;
    __stcs(&g_ALN[((size_t)ta * BATCH + b) * 256 + tid], wgt);
    __syncthreads();
    {   // ctx sweep: thread = (d4, lq)
        const int d4 = (tid & 63) * 4, lq = tid >> 6;
        const float* ew = g_ENCW + (size_t)b * 65536 + (size_t)(lq * 64) * 256 + d4;
        const float* ss = sc + lq * 64;
        float4 c4 = {0.f, 0.f, 0.f, 0.f};
#pragma unroll 8
        for (int l = 0; l < 64; l++) {
            float4 v = *(const float4*)(ew + l * 256);
            float sv = ss[l];
            c4.x += sv * v.x; c4.y += sv * v.y; c4.z += sv * v.z; c4.w += sv * v.w;
        }
        *(float4*)(sp + lq * 256 + d4) = c4;
    }
    __syncthreads();
    g_CTX[(size_t)b * 256 + tid] = (sp[tid] + sp[256 + tid]) + (sp[512 + tid] + sp[768 + tid]);
    __syncthreads();
    load_A32(g_HA[p], b0, As);
    __syncthreads();
    if (ta + 1 < TSTEPS) {
        float acc[3];
        gate3(As, sm + OWA, r, cg, acc);
        const int bm = b0 + r;
        const float* gb = g_GIA + ((size_t)bm * TSTEPS + ta + 1) * 768;
        float g0 = __ldcs(gb + c), g1 = __ldcs(gb + 256 + c), g2 = __ldcs(gb + 512 + c);
        float rr = sigm(g0 + acc[0] + attn_bhh[c]);
        float zz = sigm(g1 + acc[1] + attn_bhh[256 + c]);
        float nn = tanhf(g2 + rr * (acc[2] + attn_bhh[512 + c]));
        float hp = As[r * 260 + c];
        g_HA[p ^ 1][(size_t)bm * 256 + c] = (1.f - zz) * nn + zz * hp;
    }
    {
        const ulonglong2* a8 = (const ulonglong2*)(As + r * 260);
        const ulonglong2* w8 = (const ulonglong2*)(sm + OWR + cg * 260);
        ull acc = 0;
#pragma unroll 8
        for (int k = 0; k < 64; k++) {
            ulonglong2 a = a8[k], w2 = w8[k];
            acc = ffma2(a.x, w2.x, acc); acc = ffma2(a.y, w2.y, acc);
        }
        g_DEC[(size_t)(b0 + r) * 256 + c] = unpack_sum(acc) + proj1_b[c];
    }
}

__global__ __launch_bounds__(256) void decoder_loop(
    const float* __restrict__ attn_bhh,
    const float* __restrict__ proj1_b,
    const float* __restrict__ rnn1_bih, const float* __restrict__ rnn1_bhh,
    const float* __restrict__ rnn2_bih, const float* __restrict__ rnn2_bhh,
    const float* __restrict__ attn_whh,
    const float* __restrict__ proj1_w,
    const float* __restrict__ rnn1_wih, const float* __restrict__ rnn1_whh,
    const float* __restrict__ rnn2_wih, const float* __restrict__ rnn2_whh) {
    extern __shared__ float sm[];
    const int tid = threadIdx.x;
    const int grp = blockIdx.x >> 5, cj = blockIdx.x & 31;
    const int b0 = grp * 32, c0 = cj * 8;
    const int b = b0 + cj;
    const int r = tid >> 3, cg = tid & 7, c = c0 + cg;
    const int bm = b0 + r;
    float* T0 = sm + OST;
    float* T1 = sm + OT1;
    unsigned lgen;
    asm volatile("ld.acquire.gpu.global.u32 %0, [%1];" : "=r"(lgen) : "l"(&g_ggen[grp * 32]) : "memory");

    preload_W24(attn_whh, c0, sm + OWA);
    preload_W24(rnn1_wih, c0, sm + OW1I);
    preload_W24(rnn1_whh, c0, sm + OW1H);
    preload_W24(rnn2_wih, c0, sm + OW2I);
    preload_W24(rnn2_whh, c0, sm + OW2H);
    for (int idx = tid; idx < 8 * 64; idx += 256) {
        int row = idx >> 6, qq = idx & 63;
        *(float4*)(sm + OWR + row * 260 + qq * 4) =
            *(const float4*)(proj1_w + (size_t)(c0 + row) * 512 + 256 + qq * 4);
    }
    // prologue
    {
        int i = blockIdx.x * 256 + tid;
        g_H1[i] = 0.f;
        g_H2[i] = 0.f;
        const float* gb = g_GIA + ((size_t)bm * TSTEPS) * 768;
        float g0 = __ldcs(gb + c), g1 = __ldcs(gb + 256 + c), g2 = __ldcs(gb + 512 + c);
        float rr = sigm(g0 + attn_bhh[c]);
        float zz = sigm(g1 + attn_bhh[256 + c]);
        float nn = tanhf(g2 + rr * attn_bhh[512 + c]);
        g_HA[0][(size_t)bm * 256 + c] = (1.f - zz) * nn;
    }
    float gh1[3] = { rnn1_bhh[c], rnn1_bhh[256 + c], rnn1_bhh[512 + c] };
    float gh2[3];
    groupbar(lgen, grp, cj);
    phase_X(0, attn_bhh, proj1_b, b0, b, r, cg, c, sm);
    groupbar(lgen, grp, cj);

    for (int t = 0; t < TSTEPS; t++) {
        // ===== A(t): rnn1 + gh2(t) =====
        load_A32sum(g_CTX, g_DEC, b0, T0);
        load_A32(g_H2, b0, T1);
        __syncthreads();
        {
            float acc[3];
            gate3(T0, sm + OW1I, r, cg, acc);
            float rr = sigm(acc[0] + rnn1_bih[c] + gh1[0]);
            float zz = sigm(acc[1] + rnn1_bih[256 + c] + gh1[1]);
            float nn = tanhf(acc[2] + rnn1_bih[512 + c] + rr * gh1[2]);
            float hp = g_H1[(size_t)bm * 256 + c];
            float hn = (1.f - zz) * nn + zz * hp;
            g_H1[(size_t)bm * 256 + c] = hn;
            g_Y1[(size_t)bm * 256 + c] = T0[r * 260 + c] + hn;
        }
        gate3(T1, sm + OW2H, r, cg, gh2);
        gh2[0] += rnn2_bhh[c]; gh2[1] += rnn2_bhh[256 + c]; gh2[2] += rnn2_bhh[512 + c];
        groupbar(lgen, grp, cj);
        // ===== B(t): rnn2 + gh1(t+1) + X(t+1) =====
        load_A32(g_Y1, b0, T0);
        load_A32(g_H1, b0, T1);
        __syncthreads();
        {
            float acc[3];
            gate3(T0, sm + OW2I, r, cg, acc);
            float rr = sigm(acc[0] + rnn2_bih[c] + gh2[0]);
            float zz = sigm(acc[1] + rnn2_bih[256 + c] + gh2[1]);
            float nn = tanhf(acc[2] + rnn2_bih[512 + c] + rr * gh2[2]);
            float hp = g_H2[(size_t)bm * 256 + c];
            float hn = (1.f - zz) * nn + zz * hp;
            g_H2[(size_t)bm * 256 + c] = hn;
            __stcs(&g_Y2ALL[((size_t)bm * TSTEPS + t) * 256 + c], T0[r * 260 + c] + hn);
        }
        gate3(T1, sm + OW1H, r, cg, gh1);
        gh1[0] += rnn1_bhh[c]; gh1[1] += rnn1_bhh[256 + c]; gh1[2] += rnn1_bhh[512 + c];
        if (t + 1 < TSTEPS)
            phase_X(t + 1, attn_bhh, proj1_b, b0, b, r, cg, c, sm);
        groupbar(lgen, grp, cj);
    }
}

extern "C" void kernel_launch(void* const* d_in, const int* in_sizes, int n_in,
                              void* d_out, int out_size) {
    const float* dec      = (const float*)d_in[0];
    const float* enc      = (const float*)d_in[1];
    const float* pre_w1   = (const float*)d_in[2];
    const float* pre_b1   = (const float*)d_in[3];
    const float* pre_w2   = (const float*)d_in[4];
    const float* pre_b2   = (const float*)d_in[5];
    const float* attn_wih = (const float*)d_in[6];
    const float* attn_whh = (const float*)d_in[7];
    const float* attn_bih = (const float*)d_in[8];
    const float* attn_bhh = (const float*)d_in[9];
    const float* proj1_w  = (const float*)d_in[10];
    const float* proj1_b  = (const float*)d_in[11];
    const float* rnn1_wih = (const float*)d_in[12];
    const float* rnn1_whh = (const float*)d_in[13];
    const float* rnn1_bih = (const float*)d_in[14];
    const float* rnn1_bhh = (const float*)d_in[15];
    const float* rnn2_wih = (const float*)d_in[16];
    const float* rnn2_whh = (const float*)d_in[17];
    const float* rnn2_bih = (const float*)d_in[18];
    const float* rnn2_bhh = (const float*)d_in[19];
    const float* proj2_w  = (const float*)d_in[20];
    const float* proj2_b  = (const float*)d_in[21];
    float* out = (float*)d_out;

    float *encw, *gia, *y2all;
    cudaGetSymbolAddress((void**)&encw, g_ENCW);
    cudaGetSymbolAddress((void**)&gia, g_GIA);
    cudaGetSymbolAddress((void**)&y2all, g_Y2ALL);

    const int SMEM = SMEMF * 4;
    cudaFuncSetAttribute(decoder_loop, cudaFuncAttributeMaxDynamicSharedMemorySize, SMEM);
    const int PSMEM = (64 * 384 + 2 * 16 * 68) * 4;   // 107,008 B
    cudaFuncSetAttribute(prenet_fused_k, cudaFuncAttributeMaxDynamicSharedMemorySize, PSMEM);

    transpose_enc_k<<<dim3(128, 8, 8), 256>>>(enc);
    prenet_fused_k<<<1000, 256, PSMEM>>>(dec, pre_w1, pre_b1, pre_w2, pre_b2,
                                         attn_wih, attn_bih, gia);
    gemm_k<false, false><<<dim3(512, 4), 256>>>(enc, proj1_w, nullptr, encw, 256, 256, 512);
    decoder_loop<<<128, 256, SMEM>>>(attn_bhh, proj1_b,
                                     rnn1_bih, rnn1_bhh, rnn2_bih, rnn2_bhh,
                                     attn_whh, proj1_w,
                                     rnn1_wih, rnn1_whh, rnn2_wih, rnn2_whh);
    gemm_k<false, true><<<dim3(1000, 3), 256>>>(y2all, proj2_w, proj2_b, out, 256, 160, 256);
    transpose_aln_k<<<dim3(128, 8, 16), 256>>>(out + 10240000);
}

// round 17
// speedup vs baseline: 1.0659x; 1.0167x over previous
#include <cuda_runtime.h>
#include <cstdint>
#include <cstddef>

#define TSTEPS 500
#define BATCH  128

// smem float offsets (decoder_loop)
#define OWA  0
#define OW1I 6240
#define OW1H 12480
#define OW2I 18720
#define OW2H 24960
#define OWR  31200
#define OQ   33280
#define OSC  33536
#define OSP  33792
#define OT0  34816
#define OT1  43136
#define SMEMF 51456   /* 205,824 bytes */

__device__ float g_ENCW[128 * 256 * 256];
__device__ float g_GIA[64000 * 768];
__device__ float g_encT[128 * 256 * 256];
__device__ float g_ALN[64000 * 256];
__device__ float g_Y2ALL[64000 * 256];
__device__ float g_HA[2][128 * 256];
__device__ float g_H1[2][128 * 256];
__device__ float g_H2[2][128 * 256];
__device__ float g_CTX[2][128 * 256];
__device__ float g_DEC[2][128 * 256];
__device__ float g_Y1[2][128 * 256];
__device__ unsigned g_flag[128 * 32];
__device__ unsigned g_ggen[4 * 32];

typedef unsigned long long ull;

__device__ __forceinline__ ull ffma2(ull a, ull b, ull c) {
    ull d;
    asm("fma.rn.f32x2 %0, %1, %2, %3;" : "=l"(d) : "l"(a), "l"(b), "l"(c));
    return d;
}
__device__ __forceinline__ float unpack_sum(ull v) {
    float2 f = *(float2*)&v;
    return f.x + f.y;
}

// ---------------- generic tiled GEMM (pre/post passes) ----------------------
template <bool RELU, bool HASB>
__global__ __launch_bounds__(256) void gemm_k(const float* __restrict__ A,
                                              const float* __restrict__ W,
                                              const float* __restrict__ bias,
                                              float* __restrict__ C, int K, int N, int ldw) {
    __shared__ float As[16 * 68];
    __shared__ float Ws[16 * 68];
    const int m0 = blockIdx.x * 64, n0 = blockIdx.y * 64;
    const int tid = threadIdx.x, tx = tid & 15, ty = tid >> 4;
    float acc[4][4] = {};
    for (int k0 = 0; k0 < K; k0 += 16) {
        int idx = tid;
#pragma unroll
        for (int it = 0; it < 4; it++) {
            int m = idx >> 4, k = idx & 15;
            As[k * 68 + m] = A[(size_t)(m0 + m) * K + k0 + k];
            int wr = n0 + m;
            Ws[k * 68 + m] = (wr < N) ? W[(size_t)wr * ldw + k0 + k] : 0.f;
            idx += 256;
        }
        __syncthreads();
#pragma unroll
        for (int k = 0; k < 16; k++) {
            float4 a = *(const float4*)&As[k * 68 + ty * 4];
            float4 w = *(const float4*)&Ws[k * 68 + tx * 4];
            acc[0][0] += a.x * w.x; acc[0][1] += a.x * w.y; acc[0][2] += a.x * w.z; acc[0][3] += a.x * w.w;
            acc[1][0] += a.y * w.x; acc[1][1] += a.y * w.y; acc[1][2] += a.y * w.z; acc[1][3] += a.y * w.w;
            acc[2][0] += a.z * w.x; acc[2][1] += a.z * w.y; acc[2][2] += a.z * w.z; acc[2][3] += a.z * w.w;
            acc[3][0] += a.w * w.x; acc[3][1] += a.w * w.y; acc[3][2] += a.w * w.z; acc[3][3] += a.w * w.w;
        }
        __syncthreads();
    }
#pragma unroll
    for (int i = 0; i < 4; i++) {
        int m = m0 + ty * 4 + i;
#pragma unroll
        for (int j = 0; j < 4; j++) {
            int col = n0 + tx * 4 + j;
            if (col < N) {
                float v = acc[i][j] + (HASB ? bias[col] : 0.f);
                if (RELU) v = fmaxf(v, 0.f);
                C[(size_t)m * N + col] = v;
            }
        }
    }
}

// ---------------- fused prenet: dec -> h1 -> x2 -> gia ----------------------
template <bool RELU>
__device__ __forceinline__ void block_gemm64(const float* __restrict__ A, int lda,
                                             const float* __restrict__ W, int ldw,
                                             const float* __restrict__ bias,
                                             float* __restrict__ C, int ldc,
                                             int K, int N, float* As, float* Ws) {
    const int tid = threadIdx.x, tx = tid & 15, ty = tid >> 4;
    for (int n0 = 0; n0 < N; n0 += 64) {
        float acc[4][4] = {};
        for (int k0 = 0; k0 < K; k0 += 16) {
            int idx = tid;
#pragma unroll
            for (int it = 0; it < 4; it++) {
                int m = idx >> 4, k = idx & 15;
                As[k * 68 + m] = A[(size_t)m * lda + k0 + k];
                Ws[k * 68 + m] = W[(size_t)(n0 + m) * ldw + k0 + k];
                idx += 256;
            }
            __syncthreads();
#pragma unroll
            for (int k = 0; k < 16; k++) {
                float4 a = *(const float4*)&As[k * 68 + ty * 4];
                float4 w = *(const float4*)&Ws[k * 68 + tx * 4];
                acc[0][0] += a.x * w.x; acc[0][1] += a.x * w.y; acc[0][2] += a.x * w.z; acc[0][3] += a.x * w.w;
                acc[1][0] += a.y * w.x; acc[1][1] += a.y * w.y; acc[1][2] += a.y * w.z; acc[1][3] += a.y * w.w;
                acc[2][0] += a.z * w.x; acc[2][1] += a.z * w.y; acc[2][2] += a.z * w.z; acc[2][3] += a.z * w.w;
                acc[3][0] += a.w * w.x; acc[3][1] += a.w * w.y; acc[3][2] += a.w * w.z; acc[3][3] += a.w * w.w;
            }
            __syncthreads();
        }
#pragma unroll
        for (int i = 0; i < 4; i++) {
            int m = ty * 4 + i;
#pragma unroll
            for (int j = 0; j < 4; j++) {
                float v = acc[i][j] + bias[n0 + tx * 4 + j];
                if (RELU) v = fmaxf(v, 0.f);
                C[(size_t)m * ldc + n0 + tx * 4 + j] = v;
            }
        }
        __syncthreads();
    }
}

__global__ __launch_bounds__(256) void prenet_fused_k(
    const float* __restrict__ dec,
    const float* __restrict__ w1, const float* __restrict__ b1,
    const float* __restrict__ w2, const float* __restrict__ b2,
    const float* __restrict__ w3, const float* __restrict__ b3,
    float* __restrict__ gia) {
    extern __shared__ float psm[];
    float* h1 = psm;
    float* x2 = psm + 64 * 256;
    float* As = psm + 64 * 384;
    float* Ws = As + 16 * 68;
    const float* Arow = dec + (size_t)blockIdx.x * 64 * 80;
    block_gemm64<true>(Arow, 80, w1, 80, b1, h1, 256, 80, 256, As, Ws);
    __syncthreads();
    block_gemm64<true>(h1, 256, w2, 256, b2, x2, 128, 256, 128, As, Ws);
    __syncthreads();
    block_gemm64<false>(x2, 128, w3, 128, b3,
                        gia + (size_t)blockIdx.x * 64 * 768, 768, 128, 768, As, Ws);
}

// ---------------- transposes -----------------------------------------------
__global__ void transpose_enc_k(const float* __restrict__ enc) {
    __shared__ float tile[32][33];
    const int b = blockIdx.x, l0 = blockIdx.y * 32, d0 = blockIdx.z * 32;
    const int j = threadIdx.x & 31, i0 = threadIdx.x >> 5;
    const float* base = enc + (size_t)b * 65536;
#pragma unroll
    for (int ii = 0; ii < 32; ii += 8)
        tile[i0 + ii][j] = base[(size_t)(l0 + i0 + ii) * 256 + d0 + j];
    __syncthreads();
    float* ob = g_encT + (size_t)b * 65536;
#pragma unroll
    for (int ii = 0; ii < 32; ii += 8)
        ob[(size_t)(d0 + i0 + ii) * 256 + l0 + j] = tile[j][i0 + ii];
}

__global__ void transpose_aln_k(float* __restrict__ out) {
    __shared__ float tile[32][33];
    const int b = blockIdx.x, l0 = blockIdx.y * 32, t0 = blockIdx.z * 32;
    const int j = threadIdx.x & 31, i0 = threadIdx.x >> 5;
#pragma unroll
    for (int ii = 0; ii < 32; ii += 8) {
        int t = t0 + i0 + ii;
        if (t < TSTEPS) tile[i0 + ii][j] = g_ALN[((size_t)t * BATCH + b) * 256 + l0 + j];
    }
    __syncthreads();
#pragma unroll
    for (int ii = 0; ii < 32; ii += 8) {
        int t = t0 + j, l = l0 + i0 + ii;
        if (t < TSTEPS) out[((size_t)b * 256 + l) * TSTEPS + t] = tile[j][i0 + ii];
    }
}

// ---------------- loop helpers ----------------------------------------------
__device__ __forceinline__ float sigm(float x) { return 1.f / (1.f + expf(-x)); }

__device__ __forceinline__ void groupbar(unsigned& lgen, int grp, int cj) {
    __syncthreads();
    lgen++;
    if (cj == 0) {
        if (threadIdx.x >= 1 && threadIdx.x < 32) {
            const unsigned* f = &g_flag[(grp * 32 + threadIdx.x) * 32];
            unsigned v;
            do {
                asm volatile("ld.acquire.gpu.global.u32 %0, [%1];" : "=r"(v) : "l"(f) : "memory");
            } while ((int)(v - lgen) < 0);
        }
        __syncthreads();
        if (threadIdx.x == 0)
            asm volatile("st.release.gpu.global.u32 [%0], %1;"
                         :: "l"(&g_ggen[grp * 32]), "r"(lgen) : "memory");
    } else {
        if (threadIdx.x == 0) {
            asm volatile("st.release.gpu.global.u32 [%0], %1;"
                         :: "l"(&g_flag[blockIdx.x * 32]), "r"(lgen) : "memory");
            unsigned v;
            do {
                asm volatile("ld.acquire.gpu.global.u32 %0, [%1];"
                             : "=r"(v) : "l"(&g_ggen[grp * 32]) : "memory");
            } while ((int)(v - lgen) < 0);
        }
        __syncthreads();
    }
}

__device__ __forceinline__ void load_A32(const float* __restrict__ src, int b0, float* As) {
    for (int idx = threadIdx.x; idx < 32 * 64; idx += 256) {
        int r = idx >> 6, q = idx & 63;
        *(float4*)(As + r * 260 + q * 4) = *(const float4*)(src + (size_t)(b0 + r) * 256 + q * 4);
    }
}

__device__ __forceinline__ void load_A32sum(const float* __restrict__ sa,
                                            const float* __restrict__ sb, int b0, float* As) {
    for (int idx = threadIdx.x; idx < 32 * 64; idx += 256) {
        int r = idx >> 6, q = idx & 63;
        float4 a = *(const float4*)(sa + (size_t)(b0 + r) * 256 + q * 4);
        float4 b = *(const float4*)(sb + (size_t)(b0 + r) * 256 + q * 4);
        a.x += b.x; a.y += b.y; a.z += b.z; a.w += b.w;
        *(float4*)(As + r * 260 + q * 4) = a;
    }
}

__device__ __forceinline__ void preload_W24(const float* __restrict__ w, int c0, float* Wd) {
    for (int idx = threadIdx.x; idx < 24 * 64; idx += 256) {
        int row = idx >> 6, q = idx & 63;
        int g = row >> 3, i = row & 7;
        *(float4*)(Wd + row * 260 + q * 4) =
            *(const float4*)(w + (size_t)(g * 256 + c0 + i) * 256 + q * 4);
    }
}

__device__ __forceinline__ void gate3(const float* As, const float* Ws, int r, int cg, float out[3]) {
    const ulonglong2* a8 = (const ulonglong2*)(As + r * 260);
    const ulonglong2* w0 = (const ulonglong2*)(Ws + cg * 260);
    const ulonglong2* w1 = (const ulonglong2*)(Ws + (8 + cg) * 260);
    const ulonglong2* w2 = (const ulonglong2*)(Ws + (16 + cg) * 260);
    ull acc0 = 0, acc1 = 0, acc2 = 0;
#pragma unroll 8
    for (int k = 0; k < 64; k++) {
        ulonglong2 a = a8[k];
        ulonglong2 b0 = w0[k], b1 = w1[k], b2 = w2[k];
        acc0 = ffma2(a.x, b0.x, acc0); acc0 = ffma2(a.y, b0.y, acc0);
        acc1 = ffma2(a.x, b1.x, acc1); acc1 = ffma2(a.y, b1.y, acc1);
        acc2 = ffma2(a.x, b2.x, acc2); acc2 = ffma2(a.y, b2.y, acc2);
    }
    out[0] = unpack_sum(acc0);
    out[1] = unpack_sum(acc1);
    out[2] = unpack_sum(acc2);
}

__device__ __forceinline__ float softmax256(float s) {
    __shared__ float red[8];
    __shared__ float redv[2];
    const int tid = threadIdx.x;
    float m = s;
#pragma unroll
    for (int off = 16; off > 0; off >>= 1) m = fmaxf(m, __shfl_xor_sync(~0u, m, off));
    if ((tid & 31) == 0) red[tid >> 5] = m;
    __syncthreads();
    if (tid < 8) {
        float x = red[tid];
#pragma unroll
        for (int off = 4; off > 0; off >>= 1) x = fmaxf(x, __shfl_xor_sync(0xffu, x, off));
        if (tid == 0) redv[0] = x;
    }
    __syncthreads();
    float e = expf(s - redv[0]);
    float su = e;
#pragma unroll
    for (int off = 16; off > 0; off >>= 1) su += __shfl_xor_sync(~0u, su, off);
    if ((tid & 31) == 0) red[tid >> 5] = su;
    __syncthreads();
    if (tid < 8) {
        float x = red[tid];
#pragma unroll
        for (int off = 4; off > 0; off >>= 1) x += __shfl_xor_sync(0xffu, x, off);
        if (tid == 0) redv[1] = x;
    }
    __syncthreads();
    return e / redv[1];
}

// ---------------- single-phase pipelined decoder loop -----------------------
__global__ __launch_bounds__(256) void decoder_loop(
    const float* __restrict__ attn_bhh,
    const float* __restrict__ proj1_b,
    const float* __restrict__ rnn1_bih, const float* __restrict__ rnn1_bhh,
    const float* __restrict__ rnn2_bih, const float* __restrict__ rnn2_bhh,
    const float* __restrict__ attn_whh,
    const float* __restrict__ proj1_w,
    const float* __restrict__ rnn1_wih, const float* __restrict__ rnn1_whh,
    const float* __restrict__ rnn2_wih, const float* __restrict__ rnn2_whh) {
    extern __shared__ float sm[];
    const int tid = threadIdx.x;
    const int grp = blockIdx.x >> 5, cj = blockIdx.x & 31;
    const int b0 = grp * 32, c0 = cj * 8;
    const int b = b0 + cj;
    const int r = tid >> 3, cg = tid & 7, c = c0 + cg;
    const int bm = b0 + r;
    float* Q  = sm + OQ;
    float* SC = sm + OSC;
    float* SP = sm + OSP;
    float* T0 = sm + OT0;
    float* T1 = sm + OT1;
    unsigned lgen;
    asm volatile("ld.acquire.gpu.global.u32 %0, [%1];" : "=r"(lgen) : "l"(&g_ggen[grp * 32]) : "memory");

    preload_W24(attn_whh, c0, sm + OWA);
    preload_W24(rnn1_wih, c0, sm + OW1I);
    preload_W24(rnn1_whh, c0, sm + OW1H);
    preload_W24(rnn2_wih, c0, sm + OW2I);
    preload_W24(rnn2_whh, c0, sm + OW2H);
    for (int idx = tid; idx < 8 * 64; idx += 256) {
        int row = idx >> 6, qq = idx & 63;
        *(float4*)(sm + OWR + row * 260 + qq * 4) =
            *(const float4*)(proj1_w + (size_t)(c0 + row) * 512 + 256 + qq * 4);
    }
    // prologue: zero both parities of H1/H2; hA(0) = GRU(gia(0), 0)
    {
        int i = blockIdx.x * 256 + tid;
        g_H1[0][i] = 0.f; g_H1[1][i] = 0.f;
        g_H2[0][i] = 0.f; g_H2[1][i] = 0.f;
        const float* gb = g_GIA + ((size_t)bm * TSTEPS) * 768;
        float g0 = __ldcs(gb + c), g1 = __ldcs(gb + 256 + c), g2 = __ldcs(gb + 512 + c);
        float rr = sigm(g0 + attn_bhh[c]);
        float zz = sigm(g1 + attn_bhh[256 + c]);
        float nn = tanhf(g2 + rr * attn_bhh[512 + c]);
        g_HA[0][(size_t)bm * 256 + c] = (1.f - zz) * nn;
    }
    groupbar(lgen, grp, cj);

    for (int t = 0; t <= TSTEPS + 1; t++) {
        const bool doA  = t < TSTEPS;
        const bool doG  = (t + 1) < TSTEPS;
        const bool doR1 = (t >= 1) && (t <= TSTEPS);
        const bool doR2 = (t >= 2);
        const int pa = t & 1, pb = (t - 1) & 1;   // pa == (t-2)&1, pb == (t-3)&1

        // ---- stage 1: q + hA tile
        if (doA) {
            Q[tid] = g_HA[pa][(size_t)b * 256 + tid];
            load_A32(g_HA[pa], b0, T0);
        }
        __syncthreads();
        // scores sweep into regs (overlaps following smem work)
        float4 s4 = {0.f, 0.f, 0.f, 0.f};
        if (doA) {
            const int l4 = (tid & 63) * 4, dq = tid >> 6;
            const float* ep = g_encT + (size_t)b * 65536 + (size_t)(dq * 64) * 256 + l4;
            const float* qq = Q + dq * 64;
#pragma unroll 8
            for (int d = 0; d < 64; d++) {
                float4 v = *(const float4*)(ep + d * 256);
                float qv = qq[d];
                s4.x += qv * v.x; s4.y += qv * v.y; s4.z += qv * v.z; s4.w += qv * v.w;
            }
        }
        // attnGRU -> hA(t+1), hWr -> DEC(t)
        if (doA) {
            float acc[3];
            gate3(T0, sm + OWA, r, cg, acc);
            if (doG) {
                const float* gb = g_GIA + ((size_t)bm * TSTEPS + t + 1) * 768;
                float g0 = __ldcs(gb + c), g1 = __ldcs(gb + 256 + c), g2 = __ldcs(gb + 512 + c);
                float rr = sigm(g0 + acc[0] + attn_bhh[c]);
                float zz = sigm(g1 + acc[1] + attn_bhh[256 + c]);
                float nn = tanhf(g2 + rr * (acc[2] + attn_bhh[512 + c]));
                float hp = T0[r * 260 + c];
                g_HA[pa ^ 1][(size_t)bm * 256 + c] = (1.f - zz) * nn + zz * hp;
            }
            const ulonglong2* a8 = (const ulonglong2*)(T0 + r * 260);
            const ulonglong2* w8 = (const ulonglong2*)(sm + OWR + cg * 260);
            ull acc2 = 0;
#pragma unroll 8
            for (int k = 0; k < 64; k++) {
                ulonglong2 a = a8[k], w2 = w8[k];
                acc2 = ffma2(a.x, w2.x, acc2); acc2 = ffma2(a.y, w2.y, acc2);
            }
            g_DEC[pa][(size_t)bm * 256 + c] = unpack_sum(acc2) + proj1_b[c];
            *(float4*)(SP + (tid >> 6) * 256 + (tid & 63) * 4) = s4;
        }
        __syncthreads();   // SP ready; T0 free
        // rnn1 tile loads (overlap with softmax)
        if (doR1) {
            load_A32sum(g_CTX[pb], g_DEC[pb], b0, T0);
            load_A32(g_H1[pa], b0, T1);    // H1(t-2)
        }
        if (doA) {
            float s = (SP[tid] + SP[256 + tid]) + (SP[512 + tid] + SP[768 + tid]);
            float w = softmax256(s);
            SC[tid] = w;
            __stcs(&g_ALN[((size_t)t * BATCH + b) * 256 + tid], w);
        }
        __syncthreads();   // SC + tiles ready
        // ctx sweep into regs (overlaps rnn1 gate3s)
        float4 c4 = {0.f, 0.f, 0.f, 0.f};
        if (doA) {
            const int d4 = (tid & 63) * 4, lq = tid >> 6;
            const float* ew = g_ENCW + (size_t)b * 65536 + (size_t)(lq * 64) * 256 + d4;
            const float* ss = SC + lq * 64;
#pragma unroll 8
            for (int l = 0; l < 64; l++) {
                float4 v = *(const float4*)(ew + l * 256);
                float sv = ss[l];
                c4.x += sv * v.x; c4.y += sv * v.y; c4.z += sv * v.z; c4.w += sv * v.w;
            }
        }
        if (doR1) {   // rnn1(t-1): gh from H1(t-2), gi from dec_in(t-1)
            float gh[3], gi[3];
            gate3(T1, sm + OW1H, r, cg, gh);
            gate3(T0, sm + OW1I, r, cg, gi);
            float rr = sigm(gi[0] + rnn1_bih[c] + gh[0] + rnn1_bhh[c]);
            float zz = sigm(gi[1] + rnn1_bih[256 + c] + gh[1] + rnn1_bhh[256 + c]);
            float nn = tanhf(gi[2] + rnn1_bih[512 + c] + rr * (gh[2] + rnn1_bhh[512 + c]));
            float hp = T1[r * 260 + c];
            float hn = (1.f - zz) * nn + zz * hp;
            g_H1[pb][(size_t)bm * 256 + c] = hn;
            g_Y1[pb][(size_t)bm * 256 + c] = T0[r * 260 + c] + hn;
        }
        if (doA) *(float4*)(SP + (tid >> 6) * 256 + (tid & 63) * 4) = c4;
        __syncthreads();   // T0/T1 free; SP(ctx) ready
        if (doR2) {
            load_A32(g_Y1[pa], b0, T0);    // Y1(t-2)
            load_A32(g_H2[pb], b0, T1);    // H2(t-3)
        }
        if (doA)
            g_CTX[pa][(size_t)b * 256 + tid] =
                (SP[tid] + SP[256 + tid]) + (SP[512 + tid] + SP[768 + tid]);
        __syncthreads();   // tiles ready
        if (doR2) {   // rnn2(t-2)
            float gh[3], gi[3];
            gate3(T1, sm + OW2H, r, cg, gh);
            gate3(T0, sm + OW2I, r, cg, gi);
            float rr = sigm(gi[0] + rnn2_bih[c] + gh[0] + rnn2_bhh[c]);
            float zz = sigm(gi[1] + rnn2_bih[256 + c] + gh[1] + rnn2_bhh[256 + c]);
            float nn = tanhf(gi[2] + rnn2_bih[512 + c] + rr * (gh[2] + rnn2_bhh[512 + c]));
            float hp = T1[r * 260 + c];
            float hn = (1.f - zz) * nn + zz * hp;
            g_H2[pa][(size_t)bm * 256 + c] = hn;
            __stcs(&g_Y2ALL[((size_t)bm * TSTEPS + (t - 2)) * 256 + c], T0[r * 260 + c] + hn);
        }
        groupbar(lgen, grp, cj);
    }
}

extern "C" void kernel_launch(void* const* d_in, const int* in_sizes, int n_in,
                              void* d_out, int out_size) {
    const float* dec      = (const float*)d_in[0];
    const float* enc      = (const float*)d_in[1];
    const float* pre_w1   = (const float*)d_in[2];
    const float* pre_b1   = (const float*)d_in[3];
    const float* pre_w2   = (const float*)d_in[4];
    const float* pre_b2   = (const float*)d_in[5];
    const float* attn_wih = (const float*)d_in[6];
    const float* attn_whh = (const float*)d_in[7];
    const float* attn_bih = (const float*)d_in[8];
    const float* attn_bhh = (const float*)d_in[9];
    const float* proj1_w  = (const float*)d_in[10];
    const float* proj1_b  = (const float*)d_in[11];
    const float* rnn1_wih = (const float*)d_in[12];
    const float* rnn1_whh = (const float*)d_in[13];
    const float* rnn1_bih = (const float*)d_in[14];
    const float* rnn1_bhh = (const float*)d_in[15];
    const float* rnn2_wih = (const float*)d_in[16];
    const float* rnn2_whh = (const float*)d_in[17];
    const float* rnn2_bih = (const float*)d_in[18];
    const float* rnn2_bhh = (const float*)d_in[19];
    const float* proj2_w  = (const float*)d_in[20];
    const float* proj2_b  = (const float*)d_in[21];
    float* out = (float*)d_out;

    float *encw, *gia, *y2all;
    cudaGetSymbolAddress((void**)&encw, g_ENCW);
    cudaGetSymbolAddress((void**)&gia, g_GIA);
    cudaGetSymbolAddress((void**)&y2all, g_Y2ALL);

    const int SMEM = SMEMF * 4;
    cudaFuncSetAttribute(decoder_loop, cudaFuncAttributeMaxDynamicSharedMemorySize, SMEM);
    const int PSMEM = (64 * 384 + 2 * 16 * 68) * 4;
    cudaFuncSetAttribute(prenet_fused_k, cudaFuncAttributeMaxDynamicSharedMemorySize, PSMEM);

    transpose_enc_k<<<dim3(128, 8, 8), 256>>>(enc);
    prenet_fused_k<<<1000, 256, PSMEM>>>(dec, pre_w1, pre_b1, pre_w2, pre_b2,
                                         attn_wih, attn_bih, gia);
    gemm_k<false, false><<<dim3(512, 4), 256>>>(enc, proj1_w, nullptr, encw, 256, 256, 512);
    decoder_loop<<<128, 256, SMEM>>>(attn_bhh, proj1_b,
                                     rnn1_bih, rnn1_bhh, rnn2_bih, rnn2_bhh,
                                     attn_whh, proj1_w,
                                     rnn1_wih, rnn1_whh, rnn2_wih, rnn2_whh);
    gemm_k<false, true><<<dim3(1000, 3), 256>>>(y2all, proj2_w, proj2_b, out, 256, 160, 256);
    transpose_aln_k<<<dim3(128, 8, 16), 256>>>(out + 10240000);
}